// round 8
// baseline (speedup 1.0000x reference)
#include <cuda_runtime.h>
#include <cuda_bf16.h>
#include <cstdint>

// ---------------------------------------------------------------------------
#define Mn  16384
#define Nn  8192
#define Kn  256
#define HWn 1024
#define Bln 16

#define OUT_ZQ  (Mn * Kn)
#define OUT_IDX (2 * Mn * Kn)

#define CERT_WINDOW 3.5f
#define NCAND 16

// ---------------------------------------------------------------------------
__device__ __align__(16) int8_t g_qz[Mn * Kn];
__device__ __align__(16) int8_t g_qw[Nn * Kn];
__device__ float g_izs[Mn];
__device__ float g_iws[Nn];
__device__ float g_wnorm[Nn];
__device__ int   g_bestidx[Mn];
__device__ int   g_cand[Mn][NCAND];
__device__ int   g_flag[Mn];
__device__ int   g_flag_list[Mn];
__device__ int   g_flag_count;

// ---------------------------------------------------------------------------
__device__ __forceinline__ uint32_t smem_u32(const void* p) {
    uint32_t a;
    asm("{ .reg .u64 t; cvta.to.shared.u64 t, %1; cvt.u32.u64 %0, t; }"
        : "=r"(a) : "l"(p));
    return a;
}
__device__ __forceinline__ void cp_async16(uint32_t dst, const void* src) {
    asm volatile("cp.async.cg.shared.global [%0], [%1], 16;"
                 :: "r"(dst), "l"(src) : "memory");
}
#define MBAR_INIT(a, c) \
    asm volatile("mbarrier.init.shared.b64 [%0], %1;" :: "r"(a), "r"(c) : "memory")
#define MBAR_ARRIVE(a) \
    asm volatile("mbarrier.arrive.shared.b64 _, [%0];" :: "r"(a) : "memory")
#define CPASYNC_MBAR_ARRIVE(a) \
    asm volatile("cp.async.mbarrier.arrive.noinc.shared.b64 [%0];" :: "r"(a) : "memory")

__device__ __forceinline__ void mbar_wait(uint32_t addr, uint32_t parity) {
    asm volatile(
        "{\n\t"
        ".reg .pred P;\n\t"
        "WL_%=:\n\t"
        "mbarrier.try_wait.parity.acquire.cta.shared::cta.b64 P, [%0], %1, 0x989680;\n\t"
        "@P bra.uni WD_%=;\n\t"
        "bra.uni WL_%=;\n\t"
        "WD_%=:\n\t"
        "}"
        :: "r"(addr), "r"(parity) : "memory");
}

#define LDSM_X4(r0, r1, r2, r3, a) \
    asm volatile("ldmatrix.sync.aligned.m8n8.x4.shared.b16 {%0,%1,%2,%3}, [%4];" \
                 : "=r"(r0), "=r"(r1), "=r"(r2), "=r"(r3) : "r"(a))

#define IMMA16832(c, a, b) \
    asm volatile("mma.sync.aligned.m16n8k32.row.col.s32.s8.s8.s32 " \
                 "{%0,%1,%2,%3}, {%4,%5,%6,%7}, {%8,%9}, {%0,%1,%2,%3};" \
                 : "+r"((c)[0]), "+r"((c)[1]), "+r"((c)[2]), "+r"((c)[3]) \
                 : "r"((a)[0]), "r"((a)[1]), "r"((a)[2]), "r"((a)[3]), \
                   "r"((b)[0]), "r"((b)[1]))

// ---------------------------------------------------------------------------
// 1) Transpose: z [B,C,HW] -> z_out fp32 [B,HW,C]
// ---------------------------------------------------------------------------
__global__ void transpose_kernel(const float* __restrict__ z,
                                 float* __restrict__ zout) {
    __shared__ float tile[32][33];
    int b   = blockIdx.z;
    int hw0 = blockIdx.x * 32;
    int c0  = blockIdx.y * 32;
    const float* zp = z + (size_t)b * (Kn * HWn);
    size_t obase    = (size_t)b * (Kn * HWn);
    int tx = threadIdx.x, ty = threadIdx.y;
#pragma unroll
    for (int j = 0; j < 32; j += 8)
        tile[ty + j][tx] = zp[(c0 + ty + j) * HWn + hw0 + tx];
    __syncthreads();
#pragma unroll
    for (int j = 0; j < 32; j += 8)
        zout[obase + (size_t)(hw0 + ty + j) * Kn + c0 + tx] = tile[tx][ty + j];
}

// ---------------------------------------------------------------------------
// 2a) z row quantization
// ---------------------------------------------------------------------------
__global__ __launch_bounds__(256) void zquant_kernel(const float* __restrict__ zout) {
    int row  = (blockIdx.x * blockDim.x + threadIdx.x) >> 5;
    int lane = threadIdx.x & 31;
    const float4* zp = (const float4*)(zout + (size_t)row * Kn) + lane * 2;
    float4 v0 = zp[0], v1 = zp[1];
    float vals[8] = {v0.x, v0.y, v0.z, v0.w, v1.x, v1.y, v1.z, v1.w};
    float mx = 0.f;
#pragma unroll
    for (int j = 0; j < 8; j++) mx = fmaxf(mx, fabsf(vals[j]));
#pragma unroll
    for (int o = 16; o > 0; o >>= 1) mx = fmaxf(mx, __shfl_xor_sync(0xffffffffu, mx, o));
    mx = fmaxf(mx, 1e-20f);
    float zs = 127.f / mx;
    uint32_t p0 = 0, p1 = 0;
#pragma unroll
    for (int j = 0; j < 4; j++) {
        p0 |= ((uint32_t)(__float2int_rn(vals[j] * zs)     & 0xff)) << (8 * j);
        p1 |= ((uint32_t)(__float2int_rn(vals[4 + j] * zs) & 0xff)) << (8 * j);
    }
    *(uint2*)(g_qz + (size_t)row * Kn + lane * 8) = make_uint2(p0, p1);
    if (lane == 0) g_izs[row] = mx / 127.f;
}

// ---------------------------------------------------------------------------
// 2b) w row quantization + wnorm
// ---------------------------------------------------------------------------
__global__ __launch_bounds__(256) void wquant_kernel(const float* __restrict__ w) {
    if (blockIdx.x == 0 && threadIdx.x == 0) g_flag_count = 0;
    int row  = (blockIdx.x * blockDim.x + threadIdx.x) >> 5;
    int lane = threadIdx.x & 31;
    if (row >= Nn) return;
    const float4* wp = (const float4*)(w + (size_t)row * Kn) + lane * 2;
    float4 v0 = wp[0], v1 = wp[1];
    float vals[8] = {v0.x, v0.y, v0.z, v0.w, v1.x, v1.y, v1.z, v1.w};
    float mx = 0.f, ss = 0.f;
#pragma unroll
    for (int j = 0; j < 8; j++) { mx = fmaxf(mx, fabsf(vals[j])); ss += vals[j] * vals[j]; }
#pragma unroll
    for (int o = 16; o > 0; o >>= 1) {
        mx = fmaxf(mx, __shfl_xor_sync(0xffffffffu, mx, o));
        ss += __shfl_xor_sync(0xffffffffu, ss, o);
    }
    mx = fmaxf(mx, 1e-20f);
    float ws = 127.f / mx;
    uint32_t p0 = 0, p1 = 0;
#pragma unroll
    for (int j = 0; j < 4; j++) {
        p0 |= ((uint32_t)(__float2int_rn(vals[j] * ws)     & 0xff)) << (8 * j);
        p1 |= ((uint32_t)(__float2int_rn(vals[4 + j] * ws) & 0xff)) << (8 * j);
    }
    *(uint2*)(g_qw + (size_t)row * Kn + lane * 8) = make_uint2(p0, p1);
    if (lane == 0) {
        g_iws[row]   = mx / 127.f;
        g_wnorm[row] = 0.5f * ss;
    }
}

// ---------------------------------------------------------------------------
// 3) int8 IMMA GEMM, BM=64, 2 CTAs/SM, mbarrier-pipelined B (warp skew)
// ---------------------------------------------------------------------------
#define SM_A    0          // 16 KB
#define SM_B0   16384      // 32 KB
#define SM_B1   49152      // 32 KB
#define SM_MB   81920      // 4 mbarriers: full0, full1, empty0, empty1
#define SMEM_BYTES 82176
#define SM_MV   0
#define SM_MI   24576

#define ROWSWZ(m, c) ((uint32_t)((m) * 256 + ((((c) & 8) | (((c) ^ ((m) & 7)) & 7)) << 4)))

__global__ void __launch_bounds__(256, 2) gemm_kernel() {
    extern __shared__ char smem[];
    const uint32_t sbase = smem_u32(smem);
    const int tid  = threadIdx.x;
    const int lane = tid & 31;
    const int wid  = tid >> 5;
    const int wm   = wid >> 2;     // 0..1
    const int wn   = wid & 3;      // 0..3
    const int lj   = lane >> 3;
    const int lr   = lane & 7;
    const int m0   = blockIdx.x * 64;

    const uint32_t mb_full0  = sbase + SM_MB + 0;
    const uint32_t mb_full1  = sbase + SM_MB + 8;
    const uint32_t mb_empty0 = sbase + SM_MB + 16;
    const uint32_t mb_empty1 = sbase + SM_MB + 24;

    if (tid == 0) {
        MBAR_INIT(mb_full0, 256);
        MBAR_INIT(mb_full1, 256);
        MBAR_INIT(mb_empty0, 256);
        MBAR_INIT(mb_empty1, 256);
    }
    __syncthreads();

    // ---- prologue staging: A + B tile0 -> full0 ; B tile1 -> full1 ----
    {
        const char* srcA = (const char*)g_qz + (size_t)m0 * 256;
#pragma unroll
        for (int i = 0; i < 4; i++) {
            int f = tid + i * 256;
            int m = f >> 4, c = f & 15;
            cp_async16(sbase + SM_A + ROWSWZ(m, c), srcA + (size_t)m * 256 + c * 16);
        }
        const char* srcB = (const char*)g_qw;
#pragma unroll
        for (int i = 0; i < 8; i++) {
            int f = tid + i * 256;
            int n = f >> 4, c = f & 15;
            cp_async16(sbase + SM_B0 + ROWSWZ(n, c), srcB + (size_t)n * 256 + c * 16);
        }
        CPASYNC_MBAR_ARRIVE(mb_full0);
        srcB += 128 * 256;
#pragma unroll
        for (int i = 0; i < 8; i++) {
            int f = tid + i * 256;
            int n = f >> 4, c = f & 15;
            cp_async16(sbase + SM_B1 + ROWSWZ(n, c), srcB + (size_t)n * 256 + c * 16);
        }
        CPASYNC_MBAR_ARRIVE(mb_full1);
    }

    float izv[4];
#pragma unroll
    for (int s = 0; s < 4; s++)
        izv[s] = __ldg(&g_izs[m0 + wm * 32 + (s >> 1) * 16 + (s & 1) * 8 + (lane >> 2)]);

    // precomputed LDSM addressing: addr = rowBase + (off0 ^ (ks << 5))
    uint32_t aRow[2], aOff0[2];
#pragma unroll
    for (int mt = 0; mt < 2; mt++) {
        int ml = wm * 32 + mt * 16 + ((lj & 1) << 3) + lr;
        uint32_t cA0 = (uint32_t)(lj >> 1);   // 0 or 1
        aRow[mt]  = sbase + SM_A + (uint32_t)ml * 256;
        aOff0[mt] = (((cA0 & 8) | ((cA0 ^ (uint32_t)(ml & 7)) & 7)) << 4);
    }
    uint32_t bRel[2], bOff0[2];
#pragma unroll
    for (int p = 0; p < 2; p++) {
        int nl = wn * 32 + p * 16 + ((lj >> 1) << 3) + lr;
        uint32_t cB0 = (uint32_t)(lj & 1);
        bRel[p]  = (uint32_t)nl * 256;
        bOff0[p] = (((cB0 & 8) | ((cB0 ^ (uint32_t)(nl & 7)) & 7)) << 4);
    }

    float bv[4][6];
    int   bi[4][6];
#pragma unroll
    for (int s = 0; s < 4; s++)
#pragma unroll
        for (int e = 0; e < 6; e++) { bv[s][e] = -3.4e38f; bi[s][e] = 0; }

#define TOP6_INS(S, VAL, IDX)                                              \
    if ((VAL) > bv[S][5]) {                                                \
        float _cv = (VAL); int _ci = (IDX);                                \
        _Pragma("unroll")                                                  \
        for (int _q = 0; _q < 6; _q++) {                                   \
            if (_cv > bv[S][_q]) {                                         \
                float _tv = bv[S][_q]; int _ti = bi[S][_q];                \
                bv[S][_q] = _cv; bi[S][_q] = _ci; _cv = _tv; _ci = _ti;    \
            }                                                              \
        }                                                                  \
    }

    for (int t = 0; t < 64; t++) {
        const int s = t & 1;
        const uint32_t par = (uint32_t)((t >> 1) & 1);
        const uint32_t cur = sbase + (s ? SM_B1 : SM_B0);
        const uint32_t mb_full  = s ? mb_full1  : mb_full0;
        const uint32_t mb_empty = s ? mb_empty1 : mb_empty0;

        mbar_wait(mb_full, par);

        uint32_t bRow[2];
        bRow[0] = cur + bRel[0];
        bRow[1] = cur + bRel[1];

        int C[2][4][4];
#pragma unroll
        for (int mt = 0; mt < 2; mt++)
#pragma unroll
            for (int f = 0; f < 4; f++)
#pragma unroll
                for (int e = 0; e < 4; e++) C[mt][f][e] = 0;

#pragma unroll
        for (int ks = 0; ks < 8; ks++) {
            const uint32_t kx = (uint32_t)(ks << 5);
            uint32_t a[2][4];
#pragma unroll
            for (int mt = 0; mt < 2; mt++) {
                LDSM_X4(a[mt][0], a[mt][1], a[mt][2], a[mt][3],
                        aRow[mt] + (aOff0[mt] ^ kx));
            }
            uint32_t b[4][2];
#pragma unroll
            for (int p = 0; p < 2; p++) {
                LDSM_X4(b[2 * p][0], b[2 * p][1], b[2 * p + 1][0], b[2 * p + 1][1],
                        bRow[p] + (bOff0[p] ^ kx));
            }
#pragma unroll
            for (int mt = 0; mt < 2; mt++)
#pragma unroll
                for (int f = 0; f < 4; f++)
                    IMMA16832(C[mt][f], a[mt], b[f]);
        }

        MBAR_ARRIVE(mb_empty);

        // stage tile t+2 into this buffer (after all 256 threads released it)
        if (t <= 61) {
            mbar_wait(mb_empty, par);
            const char* src = (const char*)g_qw + (size_t)(t + 2) * 128 * 256;
#pragma unroll
            for (int i = 0; i < 8; i++) {
                int f = tid + i * 256;
                int n = f >> 4, c = f & 15;
                cp_async16(cur + ROWSWZ(n, c), src + (size_t)n * 256 + c * 16);
            }
            CPASYNC_MBAR_ARRIVE(mb_full);
        }

        // epilogue: s = izs * (Q * iws) - 0.5||w||^2 ; update top-6
        const int cbase = t * 128 + wn * 32 + 2 * (lane & 3);
#pragma unroll
        for (int f = 0; f < 4; f++) {
            float2 wv2 = __ldg((const float2*)(g_wnorm + cbase + f * 8));
            float2 iw2 = __ldg((const float2*)(g_iws  + cbase + f * 8));
            float wvv[2] = {wv2.x, wv2.y};
            float iww[2] = {iw2.x, iw2.y};
#pragma unroll
            for (int e = 0; e < 2; e++) {
                int col = cbase + f * 8 + e;
#pragma unroll
                for (int mt = 0; mt < 2; mt++) {
                    float s0 = __int2float_rn(C[mt][f][e])     * iww[e] * izv[mt * 2 + 0] - wvv[e];
                    float s1 = __int2float_rn(C[mt][f][2 + e]) * iww[e] * izv[mt * 2 + 1] - wvv[e];
                    TOP6_INS(mt * 2 + 0, s0, col);
                    TOP6_INS(mt * 2 + 1, s1, col);
                }
            }
        }
    }

    __syncthreads();

    // ---- cross-thread merge: 96 candidates/row -> top-16 ----
    float* MV = (float*)(smem + SM_MV);   // [64][96]
    int*   MI = (int*)  (smem + SM_MI);
#pragma unroll
    for (int s = 0; s < 4; s++) {
        int row = wm * 32 + (s >> 1) * 16 + (s & 1) * 8 + (lane >> 2);
        int col = (wn * 4 + (lane & 3)) * 6;
#pragma unroll
        for (int e = 0; e < 6; e++) {
            MV[row * 96 + col + e] = bv[s][e];
            MI[row * 96 + col + e] = bi[s][e];
        }
    }
    __syncthreads();

    if (tid < 64) {
        int row = tid;
        float tv[NCAND];
        int   ti[NCAND];
#pragma unroll
        for (int e = 0; e < NCAND; e++) { tv[e] = -3.4e38f; ti[e] = 0; }
        for (int k = 0; k < 96; k++) {
            float v  = MV[row * 96 + k];
            int   ix = MI[row * 96 + k];
            if (v > tv[NCAND - 1]) {
                float cv = v; int ci = ix;
#pragma unroll
                for (int q = 0; q < NCAND; q++) {
                    if (cv > tv[q]) {
                        float xv = tv[q]; int xi = ti[q];
                        tv[q] = cv; ti[q] = ci; cv = xv; ci = xi;
                    }
                }
            }
        }
        int m = m0 + row;
#pragma unroll
        for (int e = 0; e < NCAND; e++) g_cand[m][e] = ti[e];
        int fl = (tv[0] - tv[NCAND - 1] <= CERT_WINDOW) ? 1 : 0;
        g_flag[m] = fl;
        if (fl) {
            int p = atomicAdd(&g_flag_count, 1);
            g_flag_list[p] = m;
        }
    }
}

// ---------------------------------------------------------------------------
// 4) Exact fp32 rescore of top-16 candidates (one warp per row)
// ---------------------------------------------------------------------------
__global__ __launch_bounds__(256) void rescore_kernel(const float* __restrict__ zout,
                                                      const float* __restrict__ w,
                                                      float* __restrict__ idxf) {
    int m    = (blockIdx.x * blockDim.x + threadIdx.x) >> 5;
    int lane = threadIdx.x & 31;
    if (m >= Mn) return;
    if (g_flag[m]) return;

    float zr[8];
    const float* zp = zout + (size_t)m * Kn;
#pragma unroll
    for (int j = 0; j < 8; j++) zr[j] = zp[lane + 32 * j];

    float bestS = -3.4e38f;
    int   bestI = 0x7fffffff;
#pragma unroll 4
    for (int c = 0; c < NCAND; c++) {
        int idx = g_cand[m][c];
        const float* wp = w + (size_t)idx * Kn;
        float s = 0.f;
#pragma unroll
        for (int j = 0; j < 8; j++) s += zr[j] * wp[lane + 32 * j];
#pragma unroll
        for (int o = 16; o > 0; o >>= 1) s += __shfl_xor_sync(0xffffffffu, s, o);
        s -= g_wnorm[idx];
        if (s > bestS || (s == bestS && idx < bestI)) { bestS = s; bestI = idx; }
    }
    if (lane == 0) {
        g_bestidx[m] = bestI;
        idxf[m] = (float)bestI;
    }
}

// ---------------------------------------------------------------------------
// 5) Fallback full exact scan for flagged rows (expected ~0 rows)
// ---------------------------------------------------------------------------
__global__ __launch_bounds__(256) void fallback_kernel(const float* __restrict__ zout,
                                                       const float* __restrict__ w,
                                                       float* __restrict__ idxf) {
    __shared__ float sv[8];
    __shared__ int   si[8];
    int nflag = g_flag_count;
    int wi = threadIdx.x >> 5, lane = threadIdx.x & 31;
    for (int r = blockIdx.x; r < nflag; r += gridDim.x) {
        int m = g_flag_list[r];
        float zr[8];
        const float* zp = zout + (size_t)m * Kn;
#pragma unroll
        for (int j = 0; j < 8; j++) zr[j] = zp[lane + 32 * j];
        float bS = -3.4e38f;
        int   bI = 0x7fffffff;
        for (int n = wi; n < Nn; n += 8) {
            const float* wp = w + (size_t)n * Kn;
            float s = 0.f;
#pragma unroll
            for (int j = 0; j < 8; j++) s += zr[j] * wp[lane + 32 * j];
#pragma unroll
            for (int o = 16; o > 0; o >>= 1) s += __shfl_xor_sync(0xffffffffu, s, o);
            s -= g_wnorm[n];
            if (s > bS || (s == bS && n < bI)) { bS = s; bI = n; }
        }
        if (lane == 0) { sv[wi] = bS; si[wi] = bI; }
        __syncthreads();
        if (threadIdx.x == 0) {
            float bvv = sv[0]; int bii = si[0];
#pragma unroll
            for (int q = 1; q < 8; q++) {
                if (sv[q] > bvv || (sv[q] == bvv && si[q] < bii)) { bvv = sv[q]; bii = si[q]; }
            }
            g_bestidx[m] = bii;
            idxf[m] = (float)bii;
        }
        __syncthreads();
    }
}

// ---------------------------------------------------------------------------
// 6) Gather z_q
// ---------------------------------------------------------------------------
__global__ void gather_kernel(const float* __restrict__ w,
                              float* __restrict__ zq) {
    int t   = blockIdx.x * blockDim.x + threadIdx.x;
    int row = t >> 6;
    int c   = t & 63;
    int idx = g_bestidx[row];
    reinterpret_cast<float4*>(zq)[t] =
        reinterpret_cast<const float4*>(w)[(size_t)idx * 64 + c];
}

// ---------------------------------------------------------------------------
extern "C" void kernel_launch(void* const* d_in, const int* in_sizes, int n_in,
                              void* d_out, int out_size) {
    const float* z = (const float*)d_in[0];
    const float* w = (const float*)d_in[1];
    float* out   = (float*)d_out;
    float* z_out = out;
    float* z_q   = out + OUT_ZQ;
    float* idxf  = out + OUT_IDX;

    cudaFuncSetAttribute(gemm_kernel,
                         cudaFuncAttributeMaxDynamicSharedMemorySize, SMEM_BYTES);

    dim3 tt(32, 8);
    transpose_kernel<<<dim3(HWn / 32, Kn / 32, Bln), tt>>>(z, z_out);
    zquant_kernel<<<Mn / 8, 256>>>(z_out);
    wquant_kernel<<<Nn / 8, 256>>>(w);
    gemm_kernel<<<Mn / 64, 256, SMEM_BYTES>>>();
    rescore_kernel<<<Mn / 8, 256>>>(z_out, w, idxf);
    fallback_kernel<<<128, 256>>>(z_out, w, idxf);
    gather_kernel<<<(Mn * Kn / 4) / 256, 256>>>(w, z_q);
}

// round 9
// speedup vs baseline: 1.0245x; 1.0245x over previous
#include <cuda_runtime.h>
#include <cuda_bf16.h>
#include <cstdint>

// ---------------------------------------------------------------------------
#define Mn  16384
#define Nn  8192
#define Kn  256
#define HWn 1024
#define Bln 16

#define OUT_ZQ  (Mn * Kn)
#define OUT_IDX (2 * Mn * Kn)

#define CERT_WINDOW 3.5f
#define NCAND 16

// ---------------------------------------------------------------------------
__device__ __align__(16) int8_t g_qz[Mn * Kn];
__device__ __align__(16) int8_t g_qw[Nn * Kn];
__device__ float g_izs[Mn];
__device__ float g_iws[Nn];
__device__ float g_wnorm[Nn];
__device__ int   g_bestidx[Mn];
__device__ int   g_cand[Mn][NCAND];
__device__ int   g_flag[Mn];
__device__ int   g_flag_list[Mn];
__device__ int   g_flag_count;

// ---------------------------------------------------------------------------
__device__ __forceinline__ uint32_t smem_u32(const void* p) {
    uint32_t a;
    asm("{ .reg .u64 t; cvta.to.shared.u64 t, %1; cvt.u32.u64 %0, t; }"
        : "=r"(a) : "l"(p));
    return a;
}
__device__ __forceinline__ void cp_async16(uint32_t dst, const void* src) {
    asm volatile("cp.async.cg.shared.global [%0], [%1], 16;"
                 :: "r"(dst), "l"(src) : "memory");
}
#define MBAR_INIT(a, c) \
    asm volatile("mbarrier.init.shared.b64 [%0], %1;" :: "r"(a), "r"(c) : "memory")
#define MBAR_ARRIVE(a) \
    asm volatile("mbarrier.arrive.shared.b64 _, [%0];" :: "r"(a) : "memory")
#define CPASYNC_MBAR_ARRIVE(a) \
    asm volatile("cp.async.mbarrier.arrive.noinc.shared.b64 [%0];" :: "r"(a) : "memory")

__device__ __forceinline__ void mbar_wait(uint32_t addr, uint32_t parity) {
    asm volatile(
        "{\n\t"
        ".reg .pred P;\n\t"
        "WL_%=:\n\t"
        "mbarrier.try_wait.parity.acquire.cta.shared::cta.b64 P, [%0], %1, 0x989680;\n\t"
        "@P bra.uni WD_%=;\n\t"
        "bra.uni WL_%=;\n\t"
        "WD_%=:\n\t"
        "}"
        :: "r"(addr), "r"(parity) : "memory");
}

#define LDSM_X4(r0, r1, r2, r3, a) \
    asm volatile("ldmatrix.sync.aligned.m8n8.x4.shared.b16 {%0,%1,%2,%3}, [%4];" \
                 : "=r"(r0), "=r"(r1), "=r"(r2), "=r"(r3) : "r"(a))

#define IMMA16832(c, a, b) \
    asm volatile("mma.sync.aligned.m16n8k32.row.col.s32.s8.s8.s32 " \
                 "{%0,%1,%2,%3}, {%4,%5,%6,%7}, {%8,%9}, {%0,%1,%2,%3};" \
                 : "+r"((c)[0]), "+r"((c)[1]), "+r"((c)[2]), "+r"((c)[3]) \
                 : "r"((a)[0]), "r"((a)[1]), "r"((a)[2]), "r"((a)[3]), \
                   "r"((b)[0]), "r"((b)[1]))

// ---------------------------------------------------------------------------
// 1) Transpose: z [B,C,HW] -> z_out fp32 [B,HW,C]
// ---------------------------------------------------------------------------
__global__ void transpose_kernel(const float* __restrict__ z,
                                 float* __restrict__ zout) {
    __shared__ float tile[32][33];
    int b   = blockIdx.z;
    int hw0 = blockIdx.x * 32;
    int c0  = blockIdx.y * 32;
    const float* zp = z + (size_t)b * (Kn * HWn);
    size_t obase    = (size_t)b * (Kn * HWn);
    int tx = threadIdx.x, ty = threadIdx.y;
#pragma unroll
    for (int j = 0; j < 32; j += 8)
        tile[ty + j][tx] = zp[(c0 + ty + j) * HWn + hw0 + tx];
    __syncthreads();
#pragma unroll
    for (int j = 0; j < 32; j += 8)
        zout[obase + (size_t)(hw0 + ty + j) * Kn + c0 + tx] = tile[tx][ty + j];
}

// ---------------------------------------------------------------------------
// 2a) z row quantization
// ---------------------------------------------------------------------------
__global__ __launch_bounds__(256) void zquant_kernel(const float* __restrict__ zout) {
    int row  = (blockIdx.x * blockDim.x + threadIdx.x) >> 5;
    int lane = threadIdx.x & 31;
    const float4* zp = (const float4*)(zout + (size_t)row * Kn) + lane * 2;
    float4 v0 = zp[0], v1 = zp[1];
    float vals[8] = {v0.x, v0.y, v0.z, v0.w, v1.x, v1.y, v1.z, v1.w};
    float mx = 0.f;
#pragma unroll
    for (int j = 0; j < 8; j++) mx = fmaxf(mx, fabsf(vals[j]));
#pragma unroll
    for (int o = 16; o > 0; o >>= 1) mx = fmaxf(mx, __shfl_xor_sync(0xffffffffu, mx, o));
    mx = fmaxf(mx, 1e-20f);
    float zs = 127.f / mx;
    uint32_t p0 = 0, p1 = 0;
#pragma unroll
    for (int j = 0; j < 4; j++) {
        p0 |= ((uint32_t)(__float2int_rn(vals[j] * zs)     & 0xff)) << (8 * j);
        p1 |= ((uint32_t)(__float2int_rn(vals[4 + j] * zs) & 0xff)) << (8 * j);
    }
    *(uint2*)(g_qz + (size_t)row * Kn + lane * 8) = make_uint2(p0, p1);
    if (lane == 0) g_izs[row] = mx / 127.f;
}

// ---------------------------------------------------------------------------
// 2b) w row quantization + wnorm
// ---------------------------------------------------------------------------
__global__ __launch_bounds__(256) void wquant_kernel(const float* __restrict__ w) {
    if (blockIdx.x == 0 && threadIdx.x == 0) g_flag_count = 0;
    int row  = (blockIdx.x * blockDim.x + threadIdx.x) >> 5;
    int lane = threadIdx.x & 31;
    if (row >= Nn) return;
    const float4* wp = (const float4*)(w + (size_t)row * Kn) + lane * 2;
    float4 v0 = wp[0], v1 = wp[1];
    float vals[8] = {v0.x, v0.y, v0.z, v0.w, v1.x, v1.y, v1.z, v1.w};
    float mx = 0.f, ss = 0.f;
#pragma unroll
    for (int j = 0; j < 8; j++) { mx = fmaxf(mx, fabsf(vals[j])); ss += vals[j] * vals[j]; }
#pragma unroll
    for (int o = 16; o > 0; o >>= 1) {
        mx = fmaxf(mx, __shfl_xor_sync(0xffffffffu, mx, o));
        ss += __shfl_xor_sync(0xffffffffu, ss, o);
    }
    mx = fmaxf(mx, 1e-20f);
    float ws = 127.f / mx;
    uint32_t p0 = 0, p1 = 0;
#pragma unroll
    for (int j = 0; j < 4; j++) {
        p0 |= ((uint32_t)(__float2int_rn(vals[j] * ws)     & 0xff)) << (8 * j);
        p1 |= ((uint32_t)(__float2int_rn(vals[4 + j] * ws) & 0xff)) << (8 * j);
    }
    *(uint2*)(g_qw + (size_t)row * Kn + lane * 8) = make_uint2(p0, p1);
    if (lane == 0) {
        g_iws[row]   = mx / 127.f;
        g_wnorm[row] = 0.5f * ss;
    }
}

// ---------------------------------------------------------------------------
// 3) int8 IMMA GEMM, BM=64, 2 CTAs/SM, mbarrier pipeline.
//    Tile body order: wait full -> ldg prefetch -> MMA -> arrive empty ->
//    EPILOGUE -> wait empty -> stage t+2.  (epilogue overlaps peers' MMA)
// ---------------------------------------------------------------------------
#define SM_A    0          // 16 KB
#define SM_B0   16384      // 32 KB
#define SM_B1   49152      // 32 KB
#define SM_MB   81920      // 4 mbarriers
#define SMEM_BYTES 82176
#define SM_MV   0
#define SM_MI   24576

#define ROWSWZ(m, c) ((uint32_t)((m) * 256 + ((((c) & 8) | (((c) ^ ((m) & 7)) & 7)) << 4)))

__global__ void __launch_bounds__(256, 2) gemm_kernel() {
    extern __shared__ char smem[];
    const uint32_t sbase = smem_u32(smem);
    const int tid  = threadIdx.x;
    const int lane = tid & 31;
    const int wid  = tid >> 5;
    const int wm   = wid >> 2;     // 0..1
    const int wn   = wid & 3;      // 0..3
    const int lj   = lane >> 3;
    const int lr   = lane & 7;
    const int m0   = blockIdx.x * 64;

    const uint32_t mb_full0  = sbase + SM_MB + 0;
    const uint32_t mb_full1  = sbase + SM_MB + 8;
    const uint32_t mb_empty0 = sbase + SM_MB + 16;
    const uint32_t mb_empty1 = sbase + SM_MB + 24;

    if (tid == 0) {
        MBAR_INIT(mb_full0, 256);
        MBAR_INIT(mb_full1, 256);
        MBAR_INIT(mb_empty0, 256);
        MBAR_INIT(mb_empty1, 256);
    }
    __syncthreads();

    // ---- prologue staging: A + B tile0 -> full0 ; B tile1 -> full1 ----
    {
        const char* srcA = (const char*)g_qz + (size_t)m0 * 256;
#pragma unroll
        for (int i = 0; i < 4; i++) {
            int f = tid + i * 256;
            int m = f >> 4, c = f & 15;
            cp_async16(sbase + SM_A + ROWSWZ(m, c), srcA + (size_t)m * 256 + c * 16);
        }
        const char* srcB = (const char*)g_qw;
#pragma unroll
        for (int i = 0; i < 8; i++) {
            int f = tid + i * 256;
            int n = f >> 4, c = f & 15;
            cp_async16(sbase + SM_B0 + ROWSWZ(n, c), srcB + (size_t)n * 256 + c * 16);
        }
        CPASYNC_MBAR_ARRIVE(mb_full0);
        srcB += 128 * 256;
#pragma unroll
        for (int i = 0; i < 8; i++) {
            int f = tid + i * 256;
            int n = f >> 4, c = f & 15;
            cp_async16(sbase + SM_B1 + ROWSWZ(n, c), srcB + (size_t)n * 256 + c * 16);
        }
        CPASYNC_MBAR_ARRIVE(mb_full1);
    }

    float izv[4];
#pragma unroll
    for (int s = 0; s < 4; s++)
        izv[s] = __ldg(&g_izs[m0 + wm * 32 + (s >> 1) * 16 + (s & 1) * 8 + (lane >> 2)]);

    // precomputed LDSM addressing: addr = rowBase + (off0 ^ (ks << 5))
    uint32_t aRow[2], aOff0[2];
#pragma unroll
    for (int mt = 0; mt < 2; mt++) {
        int ml = wm * 32 + mt * 16 + ((lj & 1) << 3) + lr;
        uint32_t cA0 = (uint32_t)(lj >> 1);
        aRow[mt]  = sbase + SM_A + (uint32_t)ml * 256;
        aOff0[mt] = (((cA0 & 8) | ((cA0 ^ (uint32_t)(ml & 7)) & 7)) << 4);
    }
    uint32_t bRel[2], bOff0[2];
#pragma unroll
    for (int p = 0; p < 2; p++) {
        int nl = wn * 32 + p * 16 + ((lj >> 1) << 3) + lr;
        uint32_t cB0 = (uint32_t)(lj & 1);
        bRel[p]  = (uint32_t)nl * 256;
        bOff0[p] = (((cB0 & 8) | ((cB0 ^ (uint32_t)(nl & 7)) & 7)) << 4);
    }

    float bv[4][6];
    int   bi[4][6];
#pragma unroll
    for (int s = 0; s < 4; s++)
#pragma unroll
        for (int e = 0; e < 6; e++) { bv[s][e] = -3.4e38f; bi[s][e] = 0; }

#define TOP6_INS(S, VAL, IDX)                                              \
    if ((VAL) > bv[S][5]) {                                                \
        float _cv = (VAL); int _ci = (IDX);                                \
        _Pragma("unroll")                                                  \
        for (int _q = 0; _q < 6; _q++) {                                   \
            if (_cv > bv[S][_q]) {                                         \
                float _tv = bv[S][_q]; int _ti = bi[S][_q];                \
                bv[S][_q] = _cv; bi[S][_q] = _ci; _cv = _tv; _ci = _ti;    \
            }                                                              \
        }                                                                  \
    }

    for (int t = 0; t < 64; t++) {
        const int s = t & 1;
        const uint32_t par = (uint32_t)((t >> 1) & 1);
        const uint32_t cur = sbase + (s ? SM_B1 : SM_B0);
        const uint32_t mb_full  = s ? mb_full1  : mb_full0;
        const uint32_t mb_empty = s ? mb_empty1 : mb_empty0;

        mbar_wait(mb_full, par);

        // prefetch epilogue constants; latency hidden under the k-loop
        const int cbase = t * 128 + wn * 32 + 2 * (lane & 3);
        float wvv[4][2], iww[4][2];
#pragma unroll
        for (int f = 0; f < 4; f++) {
            float2 wv2 = __ldg((const float2*)(g_wnorm + cbase + f * 8));
            float2 iw2 = __ldg((const float2*)(g_iws  + cbase + f * 8));
            wvv[f][0] = wv2.x; wvv[f][1] = wv2.y;
            iww[f][0] = iw2.x; iww[f][1] = iw2.y;
        }

        uint32_t bRow[2];
        bRow[0] = cur + bRel[0];
        bRow[1] = cur + bRel[1];

        int C[2][4][4];
#pragma unroll
        for (int mt = 0; mt < 2; mt++)
#pragma unroll
            for (int f = 0; f < 4; f++)
#pragma unroll
                for (int e = 0; e < 4; e++) C[mt][f][e] = 0;

#pragma unroll
        for (int ks = 0; ks < 8; ks++) {
            const uint32_t kx = (uint32_t)(ks << 5);
            uint32_t a[2][4];
#pragma unroll
            for (int mt = 0; mt < 2; mt++) {
                LDSM_X4(a[mt][0], a[mt][1], a[mt][2], a[mt][3],
                        aRow[mt] + (aOff0[mt] ^ kx));
            }
            uint32_t b[4][2];
#pragma unroll
            for (int p = 0; p < 2; p++) {
                LDSM_X4(b[2 * p][0], b[2 * p][1], b[2 * p + 1][0], b[2 * p + 1][1],
                        bRow[p] + (bOff0[p] ^ kx));
            }
#pragma unroll
            for (int mt = 0; mt < 2; mt++)
#pragma unroll
                for (int f = 0; f < 4; f++)
                    IMMA16832(C[mt][f], a[mt], b[f]);
        }

        MBAR_ARRIVE(mb_empty);

        // ---- epilogue BEFORE the staging convergence point: overlaps
        //      other warps' IMMA phase ----
#pragma unroll
        for (int f = 0; f < 4; f++) {
#pragma unroll
            for (int e = 0; e < 2; e++) {
                int col = cbase + f * 8 + e;
#pragma unroll
                for (int mt = 0; mt < 2; mt++) {
                    float s0 = __int2float_rn(C[mt][f][e])     * iww[f][e] * izv[mt * 2 + 0] - wvv[f][e];
                    float s1 = __int2float_rn(C[mt][f][2 + e]) * iww[f][e] * izv[mt * 2 + 1] - wvv[f][e];
                    TOP6_INS(mt * 2 + 0, s0, col);
                    TOP6_INS(mt * 2 + 1, s1, col);
                }
            }
        }

        // stage tile t+2 into this buffer (after all threads released it)
        if (t <= 61) {
            mbar_wait(mb_empty, par);
            const char* src = (const char*)g_qw + (size_t)(t + 2) * 128 * 256;
#pragma unroll
            for (int i = 0; i < 8; i++) {
                int f = tid + i * 256;
                int n = f >> 4, c = f & 15;
                cp_async16(cur + ROWSWZ(n, c), src + (size_t)n * 256 + c * 16);
            }
            CPASYNC_MBAR_ARRIVE(mb_full);
        }
    }

    __syncthreads();

    // ---- cross-thread merge: 96 candidates/row -> top-16 ----
    float* MV = (float*)(smem + SM_MV);   // [64][96]
    int*   MI = (int*)  (smem + SM_MI);
#pragma unroll
    for (int s = 0; s < 4; s++) {
        int row = wm * 32 + (s >> 1) * 16 + (s & 1) * 8 + (lane >> 2);
        int col = (wn * 4 + (lane & 3)) * 6;
#pragma unroll
        for (int e = 0; e < 6; e++) {
            MV[row * 96 + col + e] = bv[s][e];
            MI[row * 96 + col + e] = bi[s][e];
        }
    }
    __syncthreads();

    if (tid < 64) {
        int row = tid;
        float tv[NCAND];
        int   ti[NCAND];
#pragma unroll
        for (int e = 0; e < NCAND; e++) { tv[e] = -3.4e38f; ti[e] = 0; }
        for (int k = 0; k < 96; k++) {
            float v  = MV[row * 96 + k];
            int   ix = MI[row * 96 + k];
            if (v > tv[NCAND - 1]) {
                float cv = v; int ci = ix;
#pragma unroll
                for (int q = 0; q < NCAND; q++) {
                    if (cv > tv[q]) {
                        float xv = tv[q]; int xi = ti[q];
                        tv[q] = cv; ti[q] = ci; cv = xv; ci = xi;
                    }
                }
            }
        }
        int m = m0 + row;
#pragma unroll
        for (int e = 0; e < NCAND; e++) g_cand[m][e] = ti[e];
        int fl = (tv[0] - tv[NCAND - 1] <= CERT_WINDOW) ? 1 : 0;
        g_flag[m] = fl;
        if (fl) {
            int p = atomicAdd(&g_flag_count, 1);
            g_flag_list[p] = m;
        }
    }
}

// ---------------------------------------------------------------------------
// 4) Exact fp32 rescore of top-16 candidates (one warp per row)
// ---------------------------------------------------------------------------
__global__ __launch_bounds__(256) void rescore_kernel(const float* __restrict__ zout,
                                                      const float* __restrict__ w,
                                                      float* __restrict__ idxf) {
    int m    = (blockIdx.x * blockDim.x + threadIdx.x) >> 5;
    int lane = threadIdx.x & 31;
    if (m >= Mn) return;
    if (g_flag[m]) return;

    float zr[8];
    const float* zp = zout + (size_t)m * Kn;
#pragma unroll
    for (int j = 0; j < 8; j++) zr[j] = zp[lane + 32 * j];

    float bestS = -3.4e38f;
    int   bestI = 0x7fffffff;
#pragma unroll 4
    for (int c = 0; c < NCAND; c++) {
        int idx = g_cand[m][c];
        const float* wp = w + (size_t)idx * Kn;
        float s = 0.f;
#pragma unroll
        for (int j = 0; j < 8; j++) s += zr[j] * wp[lane + 32 * j];
#pragma unroll
        for (int o = 16; o > 0; o >>= 1) s += __shfl_xor_sync(0xffffffffu, s, o);
        s -= g_wnorm[idx];
        if (s > bestS || (s == bestS && idx < bestI)) { bestS = s; bestI = idx; }
    }
    if (lane == 0) {
        g_bestidx[m] = bestI;
        idxf[m] = (float)bestI;
    }
}

// ---------------------------------------------------------------------------
// 5) Fallback full exact scan for flagged rows (expected ~0 rows)
// ---------------------------------------------------------------------------
__global__ __launch_bounds__(256) void fallback_kernel(const float* __restrict__ zout,
                                                       const float* __restrict__ w,
                                                       float* __restrict__ idxf) {
    __shared__ float sv[8];
    __shared__ int   si[8];
    int nflag = g_flag_count;
    int wi = threadIdx.x >> 5, lane = threadIdx.x & 31;
    for (int r = blockIdx.x; r < nflag; r += gridDim.x) {
        int m = g_flag_list[r];
        float zr[8];
        const float* zp = zout + (size_t)m * Kn;
#pragma unroll
        for (int j = 0; j < 8; j++) zr[j] = zp[lane + 32 * j];
        float bS = -3.4e38f;
        int   bI = 0x7fffffff;
        for (int n = wi; n < Nn; n += 8) {
            const float* wp = w + (size_t)n * Kn;
            float s = 0.f;
#pragma unroll
            for (int j = 0; j < 8; j++) s += zr[j] * wp[lane + 32 * j];
#pragma unroll
            for (int o = 16; o > 0; o >>= 1) s += __shfl_xor_sync(0xffffffffu, s, o);
            s -= g_wnorm[n];
            if (s > bS || (s == bS && n < bI)) { bS = s; bI = n; }
        }
        if (lane == 0) { sv[wi] = bS; si[wi] = bI; }
        __syncthreads();
        if (threadIdx.x == 0) {
            float bvv = sv[0]; int bii = si[0];
#pragma unroll
            for (int q = 1; q < 8; q++) {
                if (sv[q] > bvv || (sv[q] == bvv && si[q] < bii)) { bvv = sv[q]; bii = si[q]; }
            }
            g_bestidx[m] = bii;
            idxf[m] = (float)bii;
        }
        __syncthreads();
    }
}

// ---------------------------------------------------------------------------
// 6) Gather z_q
// ---------------------------------------------------------------------------
__global__ void gather_kernel(const float* __restrict__ w,
                              float* __restrict__ zq) {
    int t   = blockIdx.x * blockDim.x + threadIdx.x;
    int row = t >> 6;
    int c   = t & 63;
    int idx = g_bestidx[row];
    reinterpret_cast<float4*>(zq)[t] =
        reinterpret_cast<const float4*>(w)[(size_t)idx * 64 + c];
}

// ---------------------------------------------------------------------------
extern "C" void kernel_launch(void* const* d_in, const int* in_sizes, int n_in,
                              void* d_out, int out_size) {
    const float* z = (const float*)d_in[0];
    const float* w = (const float*)d_in[1];
    float* out   = (float*)d_out;
    float* z_out = out;
    float* z_q   = out + OUT_ZQ;
    float* idxf  = out + OUT_IDX;

    cudaFuncSetAttribute(gemm_kernel,
                         cudaFuncAttributeMaxDynamicSharedMemorySize, SMEM_BYTES);

    dim3 tt(32, 8);
    transpose_kernel<<<dim3(HWn / 32, Kn / 32, Bln), tt>>>(z, z_out);
    zquant_kernel<<<Mn / 8, 256>>>(z_out);
    wquant_kernel<<<Nn / 8, 256>>>(w);
    gemm_kernel<<<Mn / 64, 256, SMEM_BYTES>>>();
    rescore_kernel<<<Mn / 8, 256>>>(z_out, w, idxf);
    fallback_kernel<<<128, 256>>>(z_out, w, idxf);
    gather_kernel<<<(Mn * Kn / 4) / 256, 256>>>(w, z_q);
}